// round 1
// baseline (speedup 1.0000x reference)
#include <cuda_runtime.h>
#include <cstdint>
#include <cstring>
#include <vector>
#include <algorithm>

// ---------------------------------------------------------------------------
// CLOPLayer: out[b,c,i] = x[b,c,idx[i]] with idx a fixed permutation of the
// 224x224 grid generated by JAX threefry RNG (seed 42) + a sequential
// random-neighbor swap scan. idx is input-independent, so it is recomputed
// (deterministically, identically) on the HOST each kernel_launch call and
// shipped to the device via one captured 200KB memcpy node. The timed graph
// is: memcpy(idx) -> gather kernel (DRAM-bound, ~154MB moved).
// ---------------------------------------------------------------------------

#define GH 224
#define GW 224
#define HW (GH * GW)          // 50176
#define HW4 (HW / 4)          // 12544
#define NPLANES 384           // 128 batch * 3 channels

__device__ int g_idx[HW];

// One block per (b,c) plane. Plane (200704 B) staged in dynamic smem so the
// random gather reads hit the smem crossbar (bank-level cost) instead of
// generating 32 L1tex wavefronts per warp LDG.
__global__ __launch_bounds__(1024, 1)
void clop_gather(const float* __restrict__ x, float* __restrict__ out) {
    extern __shared__ float sp[];
    const size_t off = (size_t)blockIdx.x * HW;
    const float4* src = reinterpret_cast<const float4*>(x + off);
    float4* sp4 = reinterpret_cast<float4*>(sp);

    for (int k = threadIdx.x; k < HW4; k += 1024) {
        sp4[k] = __ldcs(&src[k]);   // streaming: plane read exactly once
    }
    __syncthreads();

    float4* dst = reinterpret_cast<float4*>(out + off);
    const int4* idx4 = reinterpret_cast<const int4*>(g_idx);

    for (int k = threadIdx.x; k < HW4; k += 1024) {
        int4 id = __ldg(&idx4[k]);  // coalesced, L2-hot across 384 blocks
        float4 v;
        v.x = sp[id.x];
        v.y = sp[id.y];
        v.z = sp[id.z];
        v.w = sp[id.w];
        __stcs(&dst[k], v);
    }
}

// ---------------------------------------------------------------------------
// Host-side exact replication of the JAX reference RNG pipeline.
// Assumes jax_threefry_partitionable = True (default since JAX 0.4.36):
//   * split(key)        -> child_j = threefry(key, (0, j))
//   * random_bits(32)   -> bits[i] = out0 ^ out1 of threefry(key, (0, i))
// ---------------------------------------------------------------------------

static inline uint32_t rotl32(uint32_t x, int d) {
    return (x << d) | (x >> (32 - d));
}

struct TFKey { uint32_t hi, lo; };

static void threefry2x32(uint32_t k0, uint32_t k1, uint32_t x0, uint32_t x1,
                         uint32_t* o0, uint32_t* o1) {
    const uint32_t ks0 = k0;
    const uint32_t ks1 = k1;
    const uint32_t ks2 = k0 ^ k1 ^ 0x1BD11BDAu;
    static const int rot_a[4] = {13, 15, 26, 6};
    static const int rot_b[4] = {17, 29, 16, 24};

    x0 += ks0;
    x1 += ks1;

    for (int i = 0; i < 4; i++) { x0 += x1; x1 = rotl32(x1, rot_a[i]); x1 ^= x0; }
    x0 += ks1; x1 += ks2 + 1u;
    for (int i = 0; i < 4; i++) { x0 += x1; x1 = rotl32(x1, rot_b[i]); x1 ^= x0; }
    x0 += ks2; x1 += ks0 + 2u;
    for (int i = 0; i < 4; i++) { x0 += x1; x1 = rotl32(x1, rot_a[i]); x1 ^= x0; }
    x0 += ks0; x1 += ks1 + 3u;
    for (int i = 0; i < 4; i++) { x0 += x1; x1 = rotl32(x1, rot_b[i]); x1 ^= x0; }
    x0 += ks1; x1 += ks2 + 4u;
    for (int i = 0; i < 4; i++) { x0 += x1; x1 = rotl32(x1, rot_a[i]); x1 ^= x0; }
    x0 += ks2; x1 += ks0 + 5u;

    *o0 = x0;
    *o1 = x1;
}

static inline TFKey tf_child(TFKey k, uint32_t j) {
    // foldlike split: child_j = threefry(key, counts=(hi=0, lo=j))
    TFKey r;
    threefry2x32(k.hi, k.lo, 0u, j, &r.hi, &r.lo);
    return r;
}

static inline uint32_t tf_bits32(TFKey k, uint32_t i) {
    // partitionable random_bits, bit_width=32: bits1 ^ bits2 at 64-bit index i
    uint32_t a, b;
    threefry2x32(k.hi, k.lo, 0u, i, &a, &b);
    return a ^ b;
}

static void compute_host_idx(int* h_idx) {
    const int n = HW;

    // key = jax.random.key(42) -> (0, 42); k1, k2 = split(key)
    TFKey key42 = {0u, 42u};
    TFKey k1 = tf_child(key42, 0u);
    TFKey k2 = tf_child(key42, 1u);

    // ---- order = jax.random.permutation(k1, n) : 2 rounds of stable
    // sort-by-random-bits (num_rounds = ceil(3*ln(50176)/ln(2^32-1)) = 2)
    std::vector<int> order(n);
    for (int i = 0; i < n; i++) order[i] = i;

    {
        TFKey cur = k1;
        std::vector<uint64_t> kv(n);
        std::vector<int> nx(n);
        for (int round = 0; round < 2; round++) {
            TFKey nkey = tf_child(cur, 0u);
            TFKey sub  = tf_child(cur, 1u);
            for (int i = 0; i < n; i++) {
                // pack (sort_key, position) -> unsigned sort == stable key sort
                kv[(size_t)i] = ((uint64_t)tf_bits32(sub, (uint32_t)i) << 32) |
                                (uint32_t)i;
            }
            std::sort(kv.begin(), kv.end());
            for (int j = 0; j < n; j++) {
                nx[(size_t)j] = order[(size_t)(uint32_t)kv[(size_t)j]];
            }
            order.swap(nx);
            cur = nkey;
        }
    }

    // ---- rs = jax.random.choice(k2, 5, (n,), p=[0.7,0.075,0.075,0.075,0.075])
    // p_cuml = fp32 cumsum; r = p_cuml[-1]*(1-uniform); ind = searchsorted_left
    float p_arr[5];
    p_arr[0] = (float)(1.0 - 0.3);
    p_arr[1] = (float)(0.3 / 4.0);
    p_arr[2] = p_arr[1];
    p_arr[3] = p_arr[1];
    p_arr[4] = p_arr[1];
    float c[5];
    c[0] = p_arr[0];
    for (int j = 1; j < 5; j++) c[j] = c[j - 1] + p_arr[j];

    std::vector<uint8_t> rs(n);
    for (int i = 0; i < n; i++) {
        uint32_t bits = tf_bits32(k2, (uint32_t)i);
        uint32_t fb = (bits >> 9) | 0x3F800000u;
        float f;
        std::memcpy(&f, &fb, 4);
        f -= 1.0f;                       // uniform in [0,1), exact in fp32
        float r = c[4] * (1.0f - f);
        int ind = 0;
        while (ind < 5 && c[ind] < r) ind++;   // searchsorted side='left'
        rs[(size_t)i] = (uint8_t)ind;
    }

    // ---- sequential random-neighbor swap scan (order-dependent, exact)
    for (int i = 0; i < n; i++) h_idx[i] = i;
    for (int t = 0; t < n; t++) {
        const int a = order[(size_t)t];
        const int r = rs[(size_t)t];
        const int i = a / GW;
        const int j = a % GW;
        const int ii = (r == 1) ? (i + 1) % GH
                     : (r == 2) ? (i + GH - 1) % GH
                     : i;
        const int jj = (r == 3) ? (j + 1) % GW
                     : (r == 4) ? (j + GW - 1) % GW
                     : j;
        const int b = (r == 0) ? a : (ii * GW + jj);
        const int va = h_idx[a];
        const int vb = h_idx[b];
        h_idx[a] = vb;
        h_idx[b] = va;
    }
}

// ---------------------------------------------------------------------------

extern "C" void kernel_launch(void* const* d_in, const int* in_sizes, int n_in,
                              void* d_out, int out_size) {
    (void)in_sizes; (void)n_in; (void)out_size;

    // Static host buffer (must outlive graph replays for the memcpy node).
    // Recomputed identically on every call — deterministic, no caching of
    // call state, same work each invocation.
    static int h_idx[HW];
    compute_host_idx(h_idx);

    cudaFuncSetAttribute(clop_gather,
                         cudaFuncAttributeMaxDynamicSharedMemorySize,
                         HW * (int)sizeof(float));

    cudaMemcpyToSymbolAsync(g_idx, h_idx, HW * sizeof(int), 0,
                            cudaMemcpyHostToDevice, 0);

    const float* x = (const float*)d_in[0];
    float* out = (float*)d_out;
    clop_gather<<<NPLANES, 1024, HW * sizeof(float)>>>(x, out);
}

// round 3
// speedup vs baseline: 1.1954x; 1.1954x over previous
#include <cuda_runtime.h>
#include <cstdint>
#include <cstring>
#include <vector>
#include <algorithm>

// ---------------------------------------------------------------------------
// CLOPLayer: out[b,c,i] = x[b,c,idx[i]], idx a fixed permutation from JAX
// threefry RNG (seed 42) + sequential neighbor-swap scan. idx is recomputed
// bit-exactly on the HOST every call (deterministic). Since swaps are local,
// displacements are small: host measures max row distance D and we gather
// band-by-band with a (BAND+2D)-row smem window and uint16 window-relative
// indices. Captured graph: memcpy(idx_local, ~100KB) -> band gather kernel.
// NOTE: no cudaHostRegister / no sync APIs — graph-capture-legal ops only.
// ---------------------------------------------------------------------------

#define GH 224
#define GW 224
#define HW (GH * GW)          // 50176
#define HW4 (HW / 4)
#define W4 (GW / 4)           // 56
#define NPLANES 384           // 128 * 3
#define BAND 28
#define NBANDS (GH / BAND)    // 8
#define BANDW (BAND * GW)     // 6272
#define BANDW4 (BANDW / 4)    // 1568

__device__ unsigned short g_idxl[HW];  // window-relative indices (banded path)
__device__ int g_idx[HW];              // absolute indices (fallback path)

// ---- banded gather: one block per (plane, band) -------------------------
__global__ __launch_bounds__(256)
void clop_band(const float* __restrict__ x, float* __restrict__ out, int L) {
    extern __shared__ float sp[];
    const int plane = blockIdx.x;
    const int band  = blockIdx.y;
    const float* src = x + (size_t)plane * HW;

    // window start row = band*BAND - D  (D = (L-BAND)/2), toroidal
    int ws = band * BAND - ((L - BAND) >> 1);
    if (ws < 0) ws += GH;

    // stage L rows (coalesced float4 per row), halo rows L2-hot
    const int n4 = L * W4;
    float4* sp4 = reinterpret_cast<float4*>(sp);
    for (int k = threadIdx.x; k < n4; k += blockDim.x) {
        int row = k / W4;
        int c4  = k - row * W4;
        int gr  = ws + row;
        if (gr >= GH) gr -= GH;
        sp4[k] = reinterpret_cast<const float4*>(src + (size_t)gr * GW)[c4];
    }
    __syncthreads();

    const size_t base = (size_t)band * BANDW;
    const ushort4* id4 = reinterpret_cast<const ushort4*>(g_idxl + base);
    float4* dst = reinterpret_cast<float4*>(out + (size_t)plane * HW + base);

    for (int k = threadIdx.x; k < BANDW4; k += blockDim.x) {
        ushort4 id = __ldg(&id4[k]);
        float4 v;
        v.x = sp[id.x];
        v.y = sp[id.y];
        v.z = sp[id.z];
        v.w = sp[id.w];
        __stcs(&dst[k], v);
    }
}

// ---- fallback: full-plane smem gather (proven correct, R1) ---------------
__global__ __launch_bounds__(1024, 1)
void clop_gather(const float* __restrict__ x, float* __restrict__ out) {
    extern __shared__ float sp[];
    const size_t off = (size_t)blockIdx.x * HW;
    const float4* src = reinterpret_cast<const float4*>(x + off);
    float4* sp4 = reinterpret_cast<float4*>(sp);
    for (int k = threadIdx.x; k < HW4; k += 1024) sp4[k] = __ldcs(&src[k]);
    __syncthreads();
    float4* dst = reinterpret_cast<float4*>(out + off);
    const int4* idx4 = reinterpret_cast<const int4*>(g_idx);
    for (int k = threadIdx.x; k < HW4; k += 1024) {
        int4 id = __ldg(&idx4[k]);
        float4 v;
        v.x = sp[id.x]; v.y = sp[id.y]; v.z = sp[id.z]; v.w = sp[id.w];
        __stcs(&dst[k], v);
    }
}

// ---------------------------------------------------------------------------
// Host-side exact replication of the JAX RNG pipeline (partitionable threefry)
// ---------------------------------------------------------------------------

static inline uint32_t rotl32(uint32_t x, int d) {
    return (x << d) | (x >> (32 - d));
}

struct TFKey { uint32_t hi, lo; };

static void threefry2x32(uint32_t k0, uint32_t k1, uint32_t x0, uint32_t x1,
                         uint32_t* o0, uint32_t* o1) {
    const uint32_t ks0 = k0, ks1 = k1, ks2 = k0 ^ k1 ^ 0x1BD11BDAu;
    static const int ra[4] = {13, 15, 26, 6};
    static const int rb[4] = {17, 29, 16, 24};
    x0 += ks0; x1 += ks1;
    for (int i = 0; i < 4; i++) { x0 += x1; x1 = rotl32(x1, ra[i]); x1 ^= x0; }
    x0 += ks1; x1 += ks2 + 1u;
    for (int i = 0; i < 4; i++) { x0 += x1; x1 = rotl32(x1, rb[i]); x1 ^= x0; }
    x0 += ks2; x1 += ks0 + 2u;
    for (int i = 0; i < 4; i++) { x0 += x1; x1 = rotl32(x1, ra[i]); x1 ^= x0; }
    x0 += ks0; x1 += ks1 + 3u;
    for (int i = 0; i < 4; i++) { x0 += x1; x1 = rotl32(x1, rb[i]); x1 ^= x0; }
    x0 += ks1; x1 += ks2 + 4u;
    for (int i = 0; i < 4; i++) { x0 += x1; x1 = rotl32(x1, ra[i]); x1 ^= x0; }
    x0 += ks2; x1 += ks0 + 5u;
    *o0 = x0; *o1 = x1;
}

static inline TFKey tf_child(TFKey k, uint32_t j) {
    TFKey r; threefry2x32(k.hi, k.lo, 0u, j, &r.hi, &r.lo); return r;
}
static inline uint32_t tf_bits32(TFKey k, uint32_t i) {
    uint32_t a, b; threefry2x32(k.hi, k.lo, 0u, i, &a, &b); return a ^ b;
}

static void compute_host_idx(int* h_idx) {
    const int n = HW;
    TFKey key42 = {0u, 42u};
    TFKey k1 = tf_child(key42, 0u);
    TFKey k2 = tf_child(key42, 1u);

    std::vector<int> order(n);
    for (int i = 0; i < n; i++) order[i] = i;
    {
        TFKey cur = k1;
        std::vector<uint64_t> kv(n);
        std::vector<int> nx(n);
        for (int round = 0; round < 2; round++) {
            TFKey nkey = tf_child(cur, 0u);
            TFKey sub  = tf_child(cur, 1u);
            for (int i = 0; i < n; i++)
                kv[(size_t)i] = ((uint64_t)tf_bits32(sub, (uint32_t)i) << 32) |
                                (uint32_t)i;
            std::sort(kv.begin(), kv.end());
            for (int j = 0; j < n; j++)
                nx[(size_t)j] = order[(size_t)(uint32_t)kv[(size_t)j]];
            order.swap(nx);
            cur = nkey;
        }
    }

    float p0 = (float)(1.0 - 0.3), pq = (float)(0.3 / 4.0);
    float c[5];
    c[0] = p0;
    for (int j = 1; j < 5; j++) c[j] = c[j - 1] + pq;

    std::vector<uint8_t> rs(n);
    for (int i = 0; i < n; i++) {
        uint32_t bits = tf_bits32(k2, (uint32_t)i);
        uint32_t fb = (bits >> 9) | 0x3F800000u;
        float f; std::memcpy(&f, &fb, 4);
        f -= 1.0f;
        float r = c[4] * (1.0f - f);
        int ind = 0;
        while (ind < 5 && c[ind] < r) ind++;
        rs[(size_t)i] = (uint8_t)ind;
    }

    for (int i = 0; i < n; i++) h_idx[i] = i;
    for (int t = 0; t < n; t++) {
        const int a = order[(size_t)t];
        const int r = rs[(size_t)t];
        const int i = a / GW, j = a % GW;
        const int ii = (r == 1) ? (i + 1) % GH : (r == 2) ? (i + GH - 1) % GH : i;
        const int jj = (r == 3) ? (j + 1) % GW : (r == 4) ? (j + GW - 1) % GW : j;
        const int b = (r == 0) ? a : (ii * GW + jj);
        const int va = h_idx[a], vb = h_idx[b];
        h_idx[a] = vb; h_idx[b] = va;
    }
}

// ---------------------------------------------------------------------------

extern "C" void kernel_launch(void* const* d_in, const int* in_sizes, int n_in,
                              void* d_out, int out_size) {
    (void)in_sizes; (void)n_in; (void)out_size;

    static int h_idx[HW];
    static unsigned short h_idxl[HW];
    compute_host_idx(h_idx);

    // measure max toroidal row distance from each output row's band window
    int D = 0;
    for (int i = 0; i < HW; i++) {
        const int r_out = i / GW;
        const int bandstart = (r_out / BAND) * BAND;
        const int r_src = h_idx[i] / GW;
        int dist = 0;
        if (r_src >= bandstart && r_src < bandstart + BAND) {
            dist = 0;
        } else {
            int dlo = (bandstart - r_src + GH) % GH;              // below window
            int dhi = (r_src - (bandstart + BAND - 1) + GH) % GH; // above window
            dist = dlo < dhi ? dlo : dhi;
        }
        if (dist > D) D = dist;
    }

    const float* x = (const float*)d_in[0];
    float* out = (float*)d_out;

    if (D <= 18) {
        // banded path
        const int L = BAND + 2 * D;
        for (int i = 0; i < HW; i++) {
            const int r_out = i / GW;
            const int ws0 = (r_out / BAND) * BAND - D;   // may be negative
            const int r_src = h_idx[i] / GW;
            const int c_src = h_idx[i] % GW;
            int t = r_src - ws0;
            t %= GH; if (t < 0) t += GH;
            h_idxl[i] = (unsigned short)(t * GW + c_src);
        }

        const int smem = L * GW * (int)sizeof(float);
        cudaFuncSetAttribute(clop_band,
                             cudaFuncAttributeMaxDynamicSharedMemorySize, smem);
        cudaMemcpyToSymbolAsync(g_idxl, h_idxl, sizeof(h_idxl), 0,
                                cudaMemcpyHostToDevice, 0);
        dim3 grid(NPLANES, NBANDS);
        clop_band<<<grid, 256, smem>>>(x, out, L);
    } else {
        // fallback: full-plane gather (R1 kernel)
        cudaFuncSetAttribute(clop_gather,
                             cudaFuncAttributeMaxDynamicSharedMemorySize,
                             HW * (int)sizeof(float));
        cudaMemcpyToSymbolAsync(g_idx, h_idx, sizeof(h_idx), 0,
                                cudaMemcpyHostToDevice, 0);
        clop_gather<<<NPLANES, 1024, HW * sizeof(float)>>>(x, out);
    }
}

// round 4
// speedup vs baseline: 1.2806x; 1.0713x over previous
#include <cuda_runtime.h>
#include <cstdint>
#include <cstring>
#include <vector>
#include <algorithm>

// ---------------------------------------------------------------------------
// CLOPLayer: out[b,c,i] = x[b,c,idx[i]], idx a fixed permutation from JAX
// threefry RNG (seed 42) + sequential neighbor-swap scan, recomputed bit-exact
// on the HOST every call. The 100KB uint16 window-relative idx table is
// delivered to the device via KERNEL PARAMETERS (4 chunks x ~32KB, baked into
// the graph exec at instantiation) — zero host->device traffic per replay,
// replacing the ~18us pageable-memcpy node of R3.
// Graph: 4 param-writer kernels -> banded gather kernel.
// ---------------------------------------------------------------------------

#define GH 224
#define GW 224
#define HW (GH * GW)          // 50176
#define HW4 (HW / 4)
#define W4 (GW / 4)           // 56
#define NPLANES 384           // 128 * 3
#define BAND 28
#define NBANDS (GH / BAND)    // 8
#define BANDW (BAND * GW)     // 6272
#define BANDW4 (BANDW / 4)    // 1568

#define CHUNK 16000           // uint16 elems per param chunk (32,000 B)
#define NCHUNKS ((HW + CHUNK - 1) / CHUNK)   // 4

__device__ unsigned short g_idxl[HW];  // window-relative indices (banded path)
__device__ int g_idx[HW];              // absolute indices (fallback path)

// ---- param-space -> device-global idx writer ------------------------------
struct IdxChunk { unsigned short v[CHUNK]; };   // 32,000 B (param limit 32,764)

__global__ __launch_bounds__(256)
void write_idx_chunk(const __grid_constant__ IdxChunk ch, int off16, int n16) {
    // copy 16B vectors: off16/n16 are in uint4 (8-elem) units
    int i = blockIdx.x * blockDim.x + threadIdx.x;
    if (i < n16) {
        const uint4* s = reinterpret_cast<const uint4*>(ch.v);
        reinterpret_cast<uint4*>(g_idxl)[off16 + i] = s[i];
    }
}

// ---- banded gather: one block per (plane, band) ---------------------------
__global__ __launch_bounds__(256)
void clop_band(const float* __restrict__ x, float* __restrict__ out, int L) {
    extern __shared__ float sp[];
    const int plane = blockIdx.x;
    const int band  = blockIdx.y;
    const float* src = x + (size_t)plane * HW;

    int ws = band * BAND - ((L - BAND) >> 1);    // window start row (toroidal)
    if (ws < 0) ws += GH;

    const int n4 = L * W4;
    float4* sp4 = reinterpret_cast<float4*>(sp);
    for (int k = threadIdx.x; k < n4; k += blockDim.x) {
        int row = k / W4;
        int c4  = k - row * W4;
        int gr  = ws + row;
        if (gr >= GH) gr -= GH;
        sp4[k] = reinterpret_cast<const float4*>(src + (size_t)gr * GW)[c4];
    }
    __syncthreads();

    const size_t base = (size_t)band * BANDW;
    const ushort4* id4 = reinterpret_cast<const ushort4*>(g_idxl + base);
    float4* dst = reinterpret_cast<float4*>(out + (size_t)plane * HW + base);

#pragma unroll 4
    for (int k = threadIdx.x; k < BANDW4; k += blockDim.x) {
        ushort4 id = __ldg(&id4[k]);
        float4 v;
        v.x = sp[id.x];
        v.y = sp[id.y];
        v.z = sp[id.z];
        v.w = sp[id.w];
        __stcs(&dst[k], v);
    }
}

// ---- fallback: full-plane smem gather (proven, R1) ------------------------
__global__ __launch_bounds__(1024, 1)
void clop_gather(const float* __restrict__ x, float* __restrict__ out) {
    extern __shared__ float sp[];
    const size_t off = (size_t)blockIdx.x * HW;
    const float4* src = reinterpret_cast<const float4*>(x + off);
    float4* sp4 = reinterpret_cast<float4*>(sp);
    for (int k = threadIdx.x; k < HW4; k += 1024) sp4[k] = src[k];
    __syncthreads();
    float4* dst = reinterpret_cast<float4*>(out + off);
    const int4* idx4 = reinterpret_cast<const int4*>(g_idx);
    for (int k = threadIdx.x; k < HW4; k += 1024) {
        int4 id = __ldg(&idx4[k]);
        float4 v;
        v.x = sp[id.x]; v.y = sp[id.y]; v.z = sp[id.z]; v.w = sp[id.w];
        __stcs(&dst[k], v);
    }
}

// ---------------------------------------------------------------------------
// Host-side exact replication of the JAX RNG pipeline (partitionable threefry)
// ---------------------------------------------------------------------------

static inline uint32_t rotl32(uint32_t x, int d) {
    return (x << d) | (x >> (32 - d));
}

struct TFKey { uint32_t hi, lo; };

static void threefry2x32(uint32_t k0, uint32_t k1, uint32_t x0, uint32_t x1,
                         uint32_t* o0, uint32_t* o1) {
    const uint32_t ks0 = k0, ks1 = k1, ks2 = k0 ^ k1 ^ 0x1BD11BDAu;
    static const int ra[4] = {13, 15, 26, 6};
    static const int rb[4] = {17, 29, 16, 24};
    x0 += ks0; x1 += ks1;
    for (int i = 0; i < 4; i++) { x0 += x1; x1 = rotl32(x1, ra[i]); x1 ^= x0; }
    x0 += ks1; x1 += ks2 + 1u;
    for (int i = 0; i < 4; i++) { x0 += x1; x1 = rotl32(x1, rb[i]); x1 ^= x0; }
    x0 += ks2; x1 += ks0 + 2u;
    for (int i = 0; i < 4; i++) { x0 += x1; x1 = rotl32(x1, ra[i]); x1 ^= x0; }
    x0 += ks0; x1 += ks1 + 3u;
    for (int i = 0; i < 4; i++) { x0 += x1; x1 = rotl32(x1, rb[i]); x1 ^= x0; }
    x0 += ks1; x1 += ks2 + 4u;
    for (int i = 0; i < 4; i++) { x0 += x1; x1 = rotl32(x1, ra[i]); x1 ^= x0; }
    x0 += ks2; x1 += ks0 + 5u;
    *o0 = x0; *o1 = x1;
}

static inline TFKey tf_child(TFKey k, uint32_t j) {
    TFKey r; threefry2x32(k.hi, k.lo, 0u, j, &r.hi, &r.lo); return r;
}
static inline uint32_t tf_bits32(TFKey k, uint32_t i) {
    uint32_t a, b; threefry2x32(k.hi, k.lo, 0u, i, &a, &b); return a ^ b;
}

static void compute_host_idx(int* h_idx) {
    const int n = HW;
    TFKey key42 = {0u, 42u};
    TFKey k1 = tf_child(key42, 0u);
    TFKey k2 = tf_child(key42, 1u);

    std::vector<int> order(n);
    for (int i = 0; i < n; i++) order[i] = i;
    {
        TFKey cur = k1;
        std::vector<uint64_t> kv(n);
        std::vector<int> nx(n);
        for (int round = 0; round < 2; round++) {
            TFKey nkey = tf_child(cur, 0u);
            TFKey sub  = tf_child(cur, 1u);
            for (int i = 0; i < n; i++)
                kv[(size_t)i] = ((uint64_t)tf_bits32(sub, (uint32_t)i) << 32) |
                                (uint32_t)i;
            std::sort(kv.begin(), kv.end());
            for (int j = 0; j < n; j++)
                nx[(size_t)j] = order[(size_t)(uint32_t)kv[(size_t)j]];
            order.swap(nx);
            cur = nkey;
        }
    }

    float p0 = (float)(1.0 - 0.3), pq = (float)(0.3 / 4.0);
    float c[5];
    c[0] = p0;
    for (int j = 1; j < 5; j++) c[j] = c[j - 1] + pq;

    std::vector<uint8_t> rs(n);
    for (int i = 0; i < n; i++) {
        uint32_t bits = tf_bits32(k2, (uint32_t)i);
        uint32_t fb = (bits >> 9) | 0x3F800000u;
        float f; std::memcpy(&f, &fb, 4);
        f -= 1.0f;
        float r = c[4] * (1.0f - f);
        int ind = 0;
        while (ind < 5 && c[ind] < r) ind++;
        rs[(size_t)i] = (uint8_t)ind;
    }

    for (int i = 0; i < n; i++) h_idx[i] = i;
    for (int t = 0; t < n; t++) {
        const int a = order[(size_t)t];
        const int r = rs[(size_t)t];
        const int i = a / GW, j = a % GW;
        const int ii = (r == 1) ? (i + 1) % GH : (r == 2) ? (i + GH - 1) % GH : i;
        const int jj = (r == 3) ? (j + 1) % GW : (r == 4) ? (j + GW - 1) % GW : j;
        const int b = (r == 0) ? a : (ii * GW + jj);
        const int va = h_idx[a], vb = h_idx[b];
        h_idx[a] = vb; h_idx[b] = va;
    }
}

// ---------------------------------------------------------------------------

extern "C" void kernel_launch(void* const* d_in, const int* in_sizes, int n_in,
                              void* d_out, int out_size) {
    (void)in_sizes; (void)n_in; (void)out_size;

    static int h_idx[HW];
    static unsigned short h_idxl[HW];
    compute_host_idx(h_idx);

    // max toroidal row distance from each output row's band window
    int D = 0;
    for (int i = 0; i < HW; i++) {
        const int r_out = i / GW;
        const int bandstart = (r_out / BAND) * BAND;
        const int r_src = h_idx[i] / GW;
        int dist = 0;
        if (r_src >= bandstart && r_src < bandstart + BAND) {
            dist = 0;
        } else {
            int dlo = (bandstart - r_src + GH) % GH;
            int dhi = (r_src - (bandstart + BAND - 1) + GH) % GH;
            dist = dlo < dhi ? dlo : dhi;
        }
        if (dist > D) D = dist;
    }

    const float* x = (const float*)d_in[0];
    float* out = (float*)d_out;

    if (D <= 18) {
        const int L = BAND + 2 * D;
        for (int i = 0; i < HW; i++) {
            const int r_out = i / GW;
            const int ws0 = (r_out / BAND) * BAND - D;
            const int r_src = h_idx[i] / GW;
            const int c_src = h_idx[i] % GW;
            int t = r_src - ws0;
            t %= GH; if (t < 0) t += GH;
            h_idxl[i] = (unsigned short)(t * GW + c_src);
        }

        // ship idx via kernel params: 4 writer launches, no H2D memcpy node
        static IdxChunk ch;   // reused staging; re-filled identically each call
        for (int cidx = 0; cidx < NCHUNKS; cidx++) {
            const int e0 = cidx * CHUNK;
            const int ne = (HW - e0 < CHUNK) ? (HW - e0) : CHUNK;
            std::memcpy(ch.v, h_idxl + e0, (size_t)ne * sizeof(unsigned short));
            const int n16 = ne / 8;            // CHUNK and HW both /8
            const int off16 = e0 / 8;
            write_idx_chunk<<<(n16 + 255) / 256, 256>>>(ch, off16, n16);
        }

        const int smem = L * GW * (int)sizeof(float);
        cudaFuncSetAttribute(clop_band,
                             cudaFuncAttributeMaxDynamicSharedMemorySize, smem);
        dim3 grid(NPLANES, NBANDS);
        clop_band<<<grid, 256, smem>>>(x, out, L);
    } else {
        // fallback: full-plane gather with pageable idx memcpy
        cudaFuncSetAttribute(clop_gather,
                             cudaFuncAttributeMaxDynamicSharedMemorySize,
                             HW * (int)sizeof(float));
        cudaMemcpyToSymbolAsync(g_idx, h_idx, sizeof(h_idx), 0,
                                cudaMemcpyHostToDevice, 0);
        clop_gather<<<NPLANES, 1024, HW * sizeof(float)>>>(x, out);
    }
}

// round 5
// speedup vs baseline: 1.5446x; 1.2062x over previous
#include <cuda_runtime.h>
#include <cstdint>
#include <cstring>
#include <vector>
#include <algorithm>

// ---------------------------------------------------------------------------
// CLOPLayer: out[b,c,i] = x[b,c,idx[i]], idx a fixed permutation from JAX
// threefry RNG (seed 42) + sequential neighbor-swap scan, recomputed bit-exact
// on the HOST every call. idx delivery: a single copy kernel LDGs the 100KB
// host-resident uint16 table directly over NVLink-C2C (GB300 ATS,
// pageableMemoryAccess=1) into g_idxl — no H2D memcpy node, no param chunks.
// Gather: one block per (plane, band), compile-time window height Lc
// (template dispatch) so both loops fully unroll with front-batched loads.
// ---------------------------------------------------------------------------

#define GH 224
#define GW 224
#define HW (GH * GW)          // 50176
#define HW4 (HW / 4)
#define W4 (GW / 4)           // 56
#define NPLANES 384           // 128 * 3
#define BAND 28
#define NBANDS (GH / BAND)    // 8
#define BANDW (BAND * GW)     // 6272
#define BANDW4 (BANDW / 4)    // 1568
#define HW16 (HW / 8)         // 6272 uint4 units of uint16 table

__device__ unsigned short g_idxl[HW];  // window-relative indices
__device__ int g_idx[HW];              // absolute indices (fallback path)

// ---- host(ATS) -> device idx copy kernel ----------------------------------
__global__ __launch_bounds__(256)
void write_idx_ats(const uint4* __restrict__ hsrc) {
    int i = blockIdx.x * blockDim.x + threadIdx.x;
    if (i < HW16) {
        reinterpret_cast<uint4*>(g_idxl)[i] = __ldg(&hsrc[i]);
    }
}

// ---- banded gather, compile-time window height Lc --------------------------
template <int Lc>
__global__ __launch_bounds__(256)
void clop_band_t(const float* __restrict__ x, float* __restrict__ out) {
    extern __shared__ float sp[];
    const int plane = blockIdx.x;
    const int band  = blockIdx.y;
    const float* src = x + (size_t)plane * HW;

    // window start row = band*BAND - D, D = (Lc-BAND)/2, toroidal
    int ws = band * BAND - ((Lc - BAND) >> 1);
    if (ws < 0) ws += GH;

    // stage Lc rows; no division in loop: row advances by 256/56 pattern
    constexpr int N4 = Lc * W4;
    float4* sp4 = reinterpret_cast<float4*>(sp);
    {
        int row0 = threadIdx.x / W4;
        int c4   = threadIdx.x - row0 * W4;
        constexpr int ROWSTEP = 256 / W4;          // 4 (remainder handled below)
        constexpr int REM = 256 - ROWSTEP * W4;    // 32
        int row = row0;
        int cc  = c4;
#pragma unroll
        for (int k = threadIdx.x; k < N4; k += 256) {
            int gr = ws + row;
            if (gr >= GH) gr -= GH;
            sp4[row * W4 + cc] =
                reinterpret_cast<const float4*>(src + (size_t)gr * GW)[cc];
            row += ROWSTEP;
            cc += REM;
            if (cc >= W4) { cc -= W4; row += 1; }
        }
    }
    __syncthreads();

    const size_t base = (size_t)band * BANDW;
    const ushort4* id4 = reinterpret_cast<const ushort4*>(g_idxl + base);
    float4* dst = reinterpret_cast<float4*>(out + (size_t)plane * HW + base);

#pragma unroll
    for (int k = threadIdx.x; k < BANDW4; k += 256) {
        ushort4 id = __ldg(&id4[k]);
        float4 v;
        v.x = sp[id.x];
        v.y = sp[id.y];
        v.z = sp[id.z];
        v.w = sp[id.w];
        __stcs(&dst[k], v);
    }
}

// ---- fallback: full-plane smem gather (proven, R1) --------------------------
__global__ __launch_bounds__(1024, 1)
void clop_gather(const float* __restrict__ x, float* __restrict__ out) {
    extern __shared__ float sp[];
    const size_t off = (size_t)blockIdx.x * HW;
    const float4* src = reinterpret_cast<const float4*>(x + off);
    float4* sp4 = reinterpret_cast<float4*>(sp);
    for (int k = threadIdx.x; k < HW4; k += 1024) sp4[k] = src[k];
    __syncthreads();
    float4* dst = reinterpret_cast<float4*>(out + off);
    const int4* idx4 = reinterpret_cast<const int4*>(g_idx);
    for (int k = threadIdx.x; k < HW4; k += 1024) {
        int4 id = __ldg(&idx4[k]);
        float4 v;
        v.x = sp[id.x]; v.y = sp[id.y]; v.z = sp[id.z]; v.w = sp[id.w];
        __stcs(&dst[k], v);
    }
}

// ---------------------------------------------------------------------------
// Host-side exact replication of the JAX RNG pipeline (partitionable threefry)
// ---------------------------------------------------------------------------

static inline uint32_t rotl32(uint32_t x, int d) {
    return (x << d) | (x >> (32 - d));
}

struct TFKey { uint32_t hi, lo; };

static void threefry2x32(uint32_t k0, uint32_t k1, uint32_t x0, uint32_t x1,
                         uint32_t* o0, uint32_t* o1) {
    const uint32_t ks0 = k0, ks1 = k1, ks2 = k0 ^ k1 ^ 0x1BD11BDAu;
    static const int ra[4] = {13, 15, 26, 6};
    static const int rb[4] = {17, 29, 16, 24};
    x0 += ks0; x1 += ks1;
    for (int i = 0; i < 4; i++) { x0 += x1; x1 = rotl32(x1, ra[i]); x1 ^= x0; }
    x0 += ks1; x1 += ks2 + 1u;
    for (int i = 0; i < 4; i++) { x0 += x1; x1 = rotl32(x1, rb[i]); x1 ^= x0; }
    x0 += ks2; x1 += ks0 + 2u;
    for (int i = 0; i < 4; i++) { x0 += x1; x1 = rotl32(x1, ra[i]); x1 ^= x0; }
    x0 += ks0; x1 += ks1 + 3u;
    for (int i = 0; i < 4; i++) { x0 += x1; x1 = rotl32(x1, rb[i]); x1 ^= x0; }
    x0 += ks1; x1 += ks2 + 4u;
    for (int i = 0; i < 4; i++) { x0 += x1; x1 = rotl32(x1, ra[i]); x1 ^= x0; }
    x0 += ks2; x1 += ks0 + 5u;
    *o0 = x0; *o1 = x1;
}

static inline TFKey tf_child(TFKey k, uint32_t j) {
    TFKey r; threefry2x32(k.hi, k.lo, 0u, j, &r.hi, &r.lo); return r;
}
static inline uint32_t tf_bits32(TFKey k, uint32_t i) {
    uint32_t a, b; threefry2x32(k.hi, k.lo, 0u, i, &a, &b); return a ^ b;
}

static void compute_host_idx(int* h_idx) {
    const int n = HW;
    TFKey key42 = {0u, 42u};
    TFKey k1 = tf_child(key42, 0u);
    TFKey k2 = tf_child(key42, 1u);

    std::vector<int> order(n);
    for (int i = 0; i < n; i++) order[i] = i;
    {
        TFKey cur = k1;
        std::vector<uint64_t> kv(n);
        std::vector<int> nx(n);
        for (int round = 0; round < 2; round++) {
            TFKey nkey = tf_child(cur, 0u);
            TFKey sub  = tf_child(cur, 1u);
            for (int i = 0; i < n; i++)
                kv[(size_t)i] = ((uint64_t)tf_bits32(sub, (uint32_t)i) << 32) |
                                (uint32_t)i;
            std::sort(kv.begin(), kv.end());
            for (int j = 0; j < n; j++)
                nx[(size_t)j] = order[(size_t)(uint32_t)kv[(size_t)j]];
            order.swap(nx);
            cur = nkey;
        }
    }

    float p0 = (float)(1.0 - 0.3), pq = (float)(0.3 / 4.0);
    float c[5];
    c[0] = p0;
    for (int j = 1; j < 5; j++) c[j] = c[j - 1] + pq;

    std::vector<uint8_t> rs(n);
    for (int i = 0; i < n; i++) {
        uint32_t bits = tf_bits32(k2, (uint32_t)i);
        uint32_t fb = (bits >> 9) | 0x3F800000u;
        float f; std::memcpy(&f, &fb, 4);
        f -= 1.0f;
        float r = c[4] * (1.0f - f);
        int ind = 0;
        while (ind < 5 && c[ind] < r) ind++;
        rs[(size_t)i] = (uint8_t)ind;
    }

    for (int i = 0; i < n; i++) h_idx[i] = i;
    for (int t = 0; t < n; t++) {
        const int a = order[(size_t)t];
        const int r = rs[(size_t)t];
        const int i = a / GW, j = a % GW;
        const int ii = (r == 1) ? (i + 1) % GH : (r == 2) ? (i + GH - 1) % GH : i;
        const int jj = (r == 3) ? (j + 1) % GW : (r == 4) ? (j + GW - 1) % GW : j;
        const int b = (r == 0) ? a : (ii * GW + jj);
        const int va = h_idx[a], vb = h_idx[b];
        h_idx[a] = vb; h_idx[b] = va;
    }
}

// ---------------------------------------------------------------------------

template <int Lc>
static void launch_band(const float* x, float* out) {
    const int smem = Lc * GW * (int)sizeof(float);
    cudaFuncSetAttribute(clop_band_t<Lc>,
                         cudaFuncAttributeMaxDynamicSharedMemorySize, smem);
    dim3 grid(NPLANES, NBANDS);
    clop_band_t<Lc><<<grid, 256, smem>>>(x, out);
}

extern "C" void kernel_launch(void* const* d_in, const int* in_sizes, int n_in,
                              void* d_out, int out_size) {
    (void)in_sizes; (void)n_in; (void)out_size;

    static int h_idx[HW];
    // 16B-aligned host idx table, directly LDG'd by the copy kernel (ATS)
    alignas(16) static unsigned short h_idxl[HW];
    compute_host_idx(h_idx);

    // max toroidal row distance from each output row's band window
    int D = 0;
    for (int i = 0; i < HW; i++) {
        const int r_out = i / GW;
        const int bandstart = (r_out / BAND) * BAND;
        const int r_src = h_idx[i] / GW;
        int dist = 0;
        if (r_src >= bandstart && r_src < bandstart + BAND) {
            dist = 0;
        } else {
            int dlo = (bandstart - r_src + GH) % GH;
            int dhi = (r_src - (bandstart + BAND - 1) + GH) % GH;
            dist = dlo < dhi ? dlo : dhi;
        }
        if (dist > D) D = dist;
    }

    const float* x = (const float*)d_in[0];
    float* out = (float*)d_out;

    // compile-time window heights: pad L = BAND + 2D up to a template size
    int Lc = 0;
    if (D <= 2)  Lc = 32;
    else if (D <= 6)  Lc = 40;
    else if (D <= 10) Lc = 48;
    else if (D <= 18) Lc = 64;

    int ats = 0;
    cudaDeviceGetAttribute(&ats, cudaDevAttrPageableMemoryAccess, 0);

    if (Lc != 0) {
        // window-relative uint16 indices for the PADDED window (D_pad = (Lc-28)/2)
        const int Dp = (Lc - BAND) / 2;
        for (int i = 0; i < HW; i++) {
            const int r_out = i / GW;
            const int ws0 = (r_out / BAND) * BAND - Dp;
            const int r_src = h_idx[i] / GW;
            const int c_src = h_idx[i] % GW;
            int t = r_src - ws0;
            t %= GH; if (t < 0) t += GH;
            h_idxl[i] = (unsigned short)(t * GW + c_src);
        }

        if (ats) {
            write_idx_ats<<<(HW16 + 255) / 256, 256>>>(
                reinterpret_cast<const uint4*>(h_idxl));
        } else {
            cudaMemcpyToSymbolAsync(g_idxl, h_idxl, sizeof(h_idxl), 0,
                                    cudaMemcpyHostToDevice, 0);
        }

        if (Lc == 32)      launch_band<32>(x, out);
        else if (Lc == 40) launch_band<40>(x, out);
        else if (Lc == 48) launch_band<48>(x, out);
        else               launch_band<64>(x, out);
    } else {
        // fallback: full-plane gather with pageable idx memcpy
        cudaFuncSetAttribute(clop_gather,
                             cudaFuncAttributeMaxDynamicSharedMemorySize,
                             HW * (int)sizeof(float));
        cudaMemcpyToSymbolAsync(g_idx, h_idx, sizeof(h_idx), 0,
                                cudaMemcpyHostToDevice, 0);
        clop_gather<<<NPLANES, 1024, HW * sizeof(float)>>>(x, out);
    }
}